// round 2
// baseline (speedup 1.0000x reference)
#include <cuda_runtime.h>
#include <math.h>

// ---------------------------------------------------------------------------
// TropicalMLP: with temp=1, trop_linear(x;W,b) = log(exp(x) @ exp(W)^T) + b.
// Pipeline:  Ex0=exp(x) -> GEMM+log -> sort-LN+relu+exp -> GEMM+log ->
//            sort-LN+relu+exp -> GEMM+log -> out
// All GEMMs are fp32 FFMA (precision: tiny IQR in LN amplifies errors ~100x,
// so bf16/tf32 inputs are not safe at rel_err 1e-3).
// ---------------------------------------------------------------------------

#define BDIM   1024
#define KDIM   512

__device__ float g_Ew1[512 * 512];
__device__ float g_Ew2[512 * 512];
__device__ float g_Ew3[256 * 512];
__device__ float g_bufA[1024 * 512];
__device__ float g_bufB[1024 * 512];
__device__ float g_H[1024 * 512];

// ---------------------------------------------------------------------------
// Elementwise exp (n must be a multiple of 1024; grid = n/1024, 256 threads)
// ---------------------------------------------------------------------------
__global__ __launch_bounds__(256) void exp_kernel(const float* __restrict__ src,
                                                  float* __restrict__ dst) {
    int i = (blockIdx.x * 256 + threadIdx.x) * 4;
    float4 v = *reinterpret_cast<const float4*>(src + i);
    v.x = expf(v.x);
    v.y = expf(v.y);
    v.z = expf(v.z);
    v.w = expf(v.w);
    *reinterpret_cast<float4*>(dst + i) = v;
}

// ---------------------------------------------------------------------------
// GEMM + log + bias.
//   C[b, i] = logf( sum_j A[b, j] * Bw[i, j] ) + bias[i]
// A: (1024, 512) row-major, Bw: (OUT, 512) row-major, C: (1024, OUT).
// Tile: BM=32 x BN=32 x BK=16, 64 threads, 4x4 microtile per thread.
// Grid: (OUT/32, 1024/32).
// ---------------------------------------------------------------------------
__global__ __launch_bounds__(64) void gemm_log_kernel(
    const float* __restrict__ A, const float* __restrict__ Bw,
    const float* __restrict__ bias, float* __restrict__ C, int OUT) {
    __shared__ float As[16][32];
    __shared__ float Bs[16][32];

    const int tid = threadIdx.x;
    const int tx = tid & 7;        // 0..7  -> output cols, 4 each
    const int ty = tid >> 3;       // 0..7  -> batch rows,  4 each
    const int bm = blockIdx.y * 32;
    const int bn = blockIdx.x * 32;

    // load mapping: each thread loads 8 consecutive K floats of one tile row
    const int lm = tid & 31;              // row within tile
    const int lk = (tid >> 5) << 3;       // 0 or 8
    const float* Ap = A + (bm + lm) * KDIM + lk;
    const float* Bp = Bw + (bn + lm) * KDIM + lk;

    float acc[4][4] = {};

    for (int k0 = 0; k0 < KDIM; k0 += 16) {
        float4 a0 = *(const float4*)(Ap + k0);
        float4 a1 = *(const float4*)(Ap + k0 + 4);
        float4 b0 = *(const float4*)(Bp + k0);
        float4 b1 = *(const float4*)(Bp + k0 + 4);

        __syncthreads();  // previous tile's compute done before overwrite
        As[lk + 0][lm] = a0.x; As[lk + 1][lm] = a0.y;
        As[lk + 2][lm] = a0.z; As[lk + 3][lm] = a0.w;
        As[lk + 4][lm] = a1.x; As[lk + 5][lm] = a1.y;
        As[lk + 6][lm] = a1.z; As[lk + 7][lm] = a1.w;
        Bs[lk + 0][lm] = b0.x; Bs[lk + 1][lm] = b0.y;
        Bs[lk + 2][lm] = b0.z; Bs[lk + 3][lm] = b0.w;
        Bs[lk + 4][lm] = b1.x; Bs[lk + 5][lm] = b1.y;
        Bs[lk + 6][lm] = b1.z; Bs[lk + 7][lm] = b1.w;
        __syncthreads();

#pragma unroll
        for (int kk = 0; kk < 16; kk++) {
            float4 av = *(const float4*)&As[kk][ty << 2];
            float4 bv = *(const float4*)&Bs[kk][tx << 2];
            float a[4] = {av.x, av.y, av.z, av.w};
            float b[4] = {bv.x, bv.y, bv.z, bv.w};
#pragma unroll
            for (int r = 0; r < 4; r++)
#pragma unroll
                for (int s = 0; s < 4; s++)
                    acc[r][s] = fmaf(a[r], b[s], acc[r][s]);
        }
    }

    const float4 bl = *(const float4*)(bias + bn + (tx << 2));
    float bb[4] = {bl.x, bl.y, bl.z, bl.w};
#pragma unroll
    for (int r = 0; r < 4; r++) {
        float* Crow = C + (bm + (ty << 2) + r) * OUT + bn + (tx << 2);
        float4 o;
        o.x = logf(acc[r][0]) + bb[0];
        o.y = logf(acc[r][1]) + bb[1];
        o.z = logf(acc[r][2]) + bb[2];
        o.w = logf(acc[r][3]) + bb[3];
        *(float4*)Crow = o;
    }
}

// ---------------------------------------------------------------------------
// trop_layernorm (median / IQR via bitonic sort) + relu + exp.
// One CTA per row (512 elements), 256 threads.
//   med = sorted[255]                           (torch-style lower median)
//   q25 = s[127] + 0.75*(s[128]-s[127])         (jnp.quantile 'linear')
//   q75 = s[383] + 0.25*(s[384]-s[383])
//   out = exp( max( (h-med)/max(iqr,eps)*w + b, 0 ) )
// ---------------------------------------------------------------------------
__global__ __launch_bounds__(256) void ln_kernel(const float* __restrict__ H,
                                                 const float* __restrict__ w,
                                                 const float* __restrict__ b,
                                                 float* __restrict__ Exout) {
    __shared__ float h[512];
    __shared__ float s[512];
    const int row = blockIdx.x;
    const int t = threadIdx.x;
    const float* Hrow = H + row * 512;

    float v0 = Hrow[t];
    float v1 = Hrow[t + 256];
    h[t] = v0;       s[t] = v0;
    h[t + 256] = v1; s[t + 256] = v1;
    __syncthreads();

    for (int k = 2; k <= 512; k <<= 1) {
        for (int j = k >> 1; j > 0; j >>= 1) {
#pragma unroll
            for (int base = 0; base < 512; base += 256) {
                int idx = base + t;
                int l = idx ^ j;
                if (l > idx) {
                    float x = s[idx], y = s[l];
                    bool asc = ((idx & k) == 0);
                    if ((x > y) == asc) { s[idx] = y; s[l] = x; }
                }
            }
            __syncthreads();
        }
    }

    float med = s[255];
    float q25 = s[127] + 0.75f * (s[128] - s[127]);
    float q75 = s[383] + 0.25f * (s[384] - s[383]);
    float iqr = fmaxf(q75 - q25, 1e-6f);
    float inv = 1.0f / iqr;

#pragma unroll
    for (int base = 0; base < 512; base += 256) {
        int idx = base + t;
        float val = (h[idx] - med) * inv * w[idx] + b[idx];
        val = fmaxf(val, 0.0f);
        Exout[row * 512 + idx] = expf(val);
    }
}

// ---------------------------------------------------------------------------
extern "C" void kernel_launch(void* const* d_in, const int* in_sizes, int n_in,
                              void* d_out, int out_size) {
    const float* x    = (const float*)d_in[0];
    const float* w1   = (const float*)d_in[1];
    const float* b1   = (const float*)d_in[2];
    const float* ln1w = (const float*)d_in[3];
    const float* ln1b = (const float*)d_in[4];
    const float* w2   = (const float*)d_in[5];
    const float* b2   = (const float*)d_in[6];
    const float* ln2w = (const float*)d_in[7];
    const float* ln2b = (const float*)d_in[8];
    const float* w3   = (const float*)d_in[9];
    const float* b3   = (const float*)d_in[10];

    float *Ew1, *Ew2, *Ew3, *bufA, *bufB, *H;
    cudaGetSymbolAddress((void**)&Ew1, g_Ew1);
    cudaGetSymbolAddress((void**)&Ew2, g_Ew2);
    cudaGetSymbolAddress((void**)&Ew3, g_Ew3);
    cudaGetSymbolAddress((void**)&bufA, g_bufA);
    cudaGetSymbolAddress((void**)&bufB, g_bufB);
    cudaGetSymbolAddress((void**)&H, g_H);

    // exp-space precompute
    exp_kernel<<<512, 256>>>(x, bufA);    // 1024*512
    exp_kernel<<<256, 256>>>(w1, Ew1);    // 512*512
    exp_kernel<<<256, 256>>>(w2, Ew2);    // 512*512
    exp_kernel<<<128, 256>>>(w3, Ew3);    // 256*512

    dim3 g12(512 / 32, 1024 / 32);
    dim3 g3(256 / 32, 1024 / 32);

    gemm_log_kernel<<<g12, 64>>>(bufA, Ew1, b1, H, 512);
    ln_kernel<<<1024, 256>>>(H, ln1w, ln1b, bufB);
    gemm_log_kernel<<<g12, 64>>>(bufB, Ew2, b2, H, 512);
    ln_kernel<<<1024, 256>>>(H, ln2w, ln2b, bufA);
    gemm_log_kernel<<<g3, 64>>>(bufA, Ew3, b3, (float*)d_out, 256);
}

// round 3
// speedup vs baseline: 1.1312x; 1.1312x over previous
#include <cuda_runtime.h>
#include <math.h>

// ---------------------------------------------------------------------------
// TropicalMLP: with temp=1, trop_linear(x;W,b) = log(exp(x) @ exp(W)^T) + b.
// Pipeline: fused exp -> GEMM+log -> sortLN+relu+exp -> GEMM+log ->
//           sortLN+relu+exp -> GEMM+log.  All GEMMs fp32 FFMA (IQR in LN
//           amplifies GEMM rounding ~100x; bf16/tf32 unsafe at 1e-3).
// ---------------------------------------------------------------------------

#define KDIM 512

__device__ float g_Ew1[512 * 512];
__device__ float g_Ew2[512 * 512];
__device__ float g_Ew3[256 * 512];
__device__ float g_bufA[1024 * 512];
__device__ float g_bufB[1024 * 512];
__device__ float g_H[1024 * 512];

// ---------------------------------------------------------------------------
// One fused exp over all four input arrays (x, w1, w2, w3), float4-wide.
// Region sizes in float4s: 131072 / 65536 / 65536 / 32768 -> 294912 total.
// ---------------------------------------------------------------------------
__global__ __launch_bounds__(256) void exp_all_kernel(
    const float* __restrict__ x,  float* __restrict__ ex,
    const float* __restrict__ w1, float* __restrict__ e1,
    const float* __restrict__ w2, float* __restrict__ e2,
    const float* __restrict__ w3, float* __restrict__ e3) {
    int i = blockIdx.x * 256 + threadIdx.x;  // float4 index
    const float* s; float* d; int off;
    if (i < 131072)      { s = x;  d = ex; off = i; }
    else if (i < 196608) { s = w1; d = e1; off = i - 131072; }
    else if (i < 262144) { s = w2; d = e2; off = i - 196608; }
    else                 { s = w3; d = e3; off = i - 262144; }
    float4 v = reinterpret_cast<const float4*>(s)[off];
    v.x = expf(v.x); v.y = expf(v.y); v.z = expf(v.z); v.w = expf(v.w);
    reinterpret_cast<float4*>(d)[off] = v;
}

// ---------------------------------------------------------------------------
// GEMM + log + bias:  C[m,n] = log( sum_k A[m,k]*Bw[n,k] ) + bias[n]
// BM x 64 x 16 tiles, 128 threads, double-buffered smem, register prefetch.
// BM=64: 8x4 microtile (32 FFMA / 3 LDS.128 per kk).
// BM=32: 4x4 microtile.
// ---------------------------------------------------------------------------
template <int BM>
__global__ __launch_bounds__(128) void gemm_log_k(
    const float* __restrict__ A, const float* __restrict__ Bw,
    const float* __restrict__ bias, float* __restrict__ C, int OUT) {
    constexpr int BN = 64;
    constexpr int TM = BM / 8;     // 8 or 4
    constexpr int TN = 4;
    constexpr int AF = BM / 8;     // floats loaded per thread for A (8 or 4)

    __shared__ float As[2][16][BM];
    __shared__ float Bs[2][16][BN];

    const int tid = threadIdx.x;
    const int tx = tid & 15;           // 16 col groups of 4
    const int ty = tid >> 4;           // 8 row groups of TM
    const int bm = blockIdx.y * BM;
    const int bn = blockIdx.x * BN;

    // Global-load mapping: one row per thread (conflict-free STS).
    const int alr = tid % BM;
    const int alc = (tid / BM) * AF;
    const float* Ap = A + (bm + alr) * KDIM + alc;
    const int blr = tid & 63;
    const int blc = (tid >> 6) * 8;
    const float* Bp = Bw + (bn + blr) * KDIM + blc;

    float acc[TM][TN] = {};
    float ar[AF], br[8];

    // --- prologue: load tile 0 ---
#pragma unroll
    for (int i = 0; i < AF; i += 4) {
        float4 v = *(const float4*)(Ap + i);
        ar[i] = v.x; ar[i + 1] = v.y; ar[i + 2] = v.z; ar[i + 3] = v.w;
    }
#pragma unroll
    for (int i = 0; i < 8; i += 4) {
        float4 v = *(const float4*)(Bp + i);
        br[i] = v.x; br[i + 1] = v.y; br[i + 2] = v.z; br[i + 3] = v.w;
    }
#pragma unroll
    for (int i = 0; i < AF; i++) As[0][alc + i][alr] = ar[i];
#pragma unroll
    for (int i = 0; i < 8; i++)  Bs[0][blc + i][blr] = br[i];
    __syncthreads();

    for (int k0 = 16; k0 < KDIM; k0 += 16) {
        const int cur = ((k0 >> 4) - 1) & 1;
        const int nxt = cur ^ 1;

        // prefetch next tile into registers
#pragma unroll
        for (int i = 0; i < AF; i += 4) {
            float4 v = *(const float4*)(Ap + k0 + i);
            ar[i] = v.x; ar[i + 1] = v.y; ar[i + 2] = v.z; ar[i + 3] = v.w;
        }
#pragma unroll
        for (int i = 0; i < 8; i += 4) {
            float4 v = *(const float4*)(Bp + k0 + i);
            br[i] = v.x; br[i + 1] = v.y; br[i + 2] = v.z; br[i + 3] = v.w;
        }

        // compute current buffer
#pragma unroll
        for (int kk = 0; kk < 16; kk++) {
            float a[TM], b[TN];
#pragma unroll
            for (int i = 0; i < TM; i += 4) {
                float4 v = *(const float4*)&As[cur][kk][ty * TM + i];
                a[i] = v.x; a[i + 1] = v.y; a[i + 2] = v.z; a[i + 3] = v.w;
            }
            {
                float4 v = *(const float4*)&Bs[cur][kk][tx * 4];
                b[0] = v.x; b[1] = v.y; b[2] = v.z; b[3] = v.w;
            }
#pragma unroll
            for (int r = 0; r < TM; r++)
#pragma unroll
                for (int s = 0; s < TN; s++)
                    acc[r][s] = fmaf(a[r], b[s], acc[r][s]);
        }

        // store prefetched tile
#pragma unroll
        for (int i = 0; i < AF; i++) As[nxt][alc + i][alr] = ar[i];
#pragma unroll
        for (int i = 0; i < 8; i++)  Bs[nxt][blc + i][blr] = br[i];
        __syncthreads();
    }

    // last tile (buffer 1: 32 tiles -> last stored in buf ((31)&1)=1)
    {
        const int cur = ((KDIM >> 4) - 1) & 1;
#pragma unroll
        for (int kk = 0; kk < 16; kk++) {
            float a[TM], b[TN];
#pragma unroll
            for (int i = 0; i < TM; i += 4) {
                float4 v = *(const float4*)&As[cur][kk][ty * TM + i];
                a[i] = v.x; a[i + 1] = v.y; a[i + 2] = v.z; a[i + 3] = v.w;
            }
            {
                float4 v = *(const float4*)&Bs[cur][kk][tx * 4];
                b[0] = v.x; b[1] = v.y; b[2] = v.z; b[3] = v.w;
            }
#pragma unroll
            for (int r = 0; r < TM; r++)
#pragma unroll
                for (int s = 0; s < TN; s++)
                    acc[r][s] = fmaf(a[r], b[s], acc[r][s]);
        }
    }

    // epilogue: log + bias
    const float4 bl = *(const float4*)(bias + bn + tx * 4);
#pragma unroll
    for (int r = 0; r < TM; r++) {
        float4 o;
        o.x = logf(acc[r][0]) + bl.x;
        o.y = logf(acc[r][1]) + bl.y;
        o.z = logf(acc[r][2]) + bl.z;
        o.w = logf(acc[r][3]) + bl.w;
        *(float4*)(C + (bm + ty * TM + r) * OUT + bn + tx * 4) = o;
    }
}

// ---------------------------------------------------------------------------
// trop_layernorm (median/IQR via bitonic sort) + relu + exp.
// 256 threads/row; thread t holds sorted-slot t (v0) and t+256 (v1).
// Steps with j<=16 use shfl.bfly (no barriers); j=256 is an in-thread
// min/max; only 9 steps (j in {32,64,128}) touch smem. Originals stay in
// registers.
//   med = s[255]; q25 = s[127]+0.75*(s[128]-s[127]);
//   q75 = s[383]+0.25*(s[384]-s[383]);  out = exp(max(..., 0))
// ---------------------------------------------------------------------------
__global__ __launch_bounds__(256) void ln_kernel(const float* __restrict__ H,
                                                 const float* __restrict__ w,
                                                 const float* __restrict__ b,
                                                 float* __restrict__ Exout) {
    __shared__ float s[512];
    const int row = blockIdx.x;
    const int t = threadIdx.x;
    const float* Hrow = H + row * 512;

    const float h0 = Hrow[t];
    const float h1 = Hrow[t + 256];
    float v0 = h0, v1 = h1;

#pragma unroll
    for (int k = 2; k <= 512; k <<= 1) {
        if (k == 512) {  // j=256: partner is the other register of this thread
            float m = fminf(v0, v1), M = fmaxf(v0, v1);
            v0 = m; v1 = M;  // asc=true for all idx (idx&512==0)
        }
        // smem steps: j in {min(k/2,128) .. 32}
#pragma unroll
        for (int j = (k >> 1) > 128 ? 128 : (k >> 1); j >= 32; j >>= 1) {
            __syncthreads();
            s[t] = v0; s[t + 256] = v1;
            __syncthreads();
            float p0 = s[t ^ j];
            float p1 = s[(t ^ j) + 256];
            bool asc0 = ((t & k) == 0);
            bool asc1 = (((t + 256) & k) == 0);
            bool low = ((t & j) == 0);
            v0 = (low == asc0) ? fminf(v0, p0) : fmaxf(v0, p0);
            v1 = (low == asc1) ? fminf(v1, p1) : fmaxf(v1, p1);
        }
        // shfl steps: j in {min(k/2,16) .. 1}
#pragma unroll
        for (int j = (k >> 1) > 16 ? 16 : (k >> 1); j >= 1; j >>= 1) {
            bool asc0 = ((t & k) == 0);
            bool asc1 = (((t + 256) & k) == 0);
            bool low = ((t & j) == 0);
            float p0 = __shfl_xor_sync(0xffffffffu, v0, j);
            float p1 = __shfl_xor_sync(0xffffffffu, v1, j);
            v0 = (low == asc0) ? fminf(v0, p0) : fmaxf(v0, p0);
            v1 = (low == asc1) ? fminf(v1, p1) : fmaxf(v1, p1);
        }
    }

    // publish the 5 needed order statistics
    __syncthreads();
    if (t == 127) { s[0] = v0; s[3] = v1; }   // sorted[127], sorted[383]
    if (t == 128) { s[1] = v0; s[4] = v1; }   // sorted[128], sorted[384]
    if (t == 255) { s[2] = v0; }              // sorted[255] (median)
    __syncthreads();
    const float q25 = s[0] + 0.75f * (s[1] - s[0]);
    const float med = s[2];
    const float q75 = s[3] + 0.25f * (s[4] - s[3]);
    const float inv = 1.0f / fmaxf(q75 - q25, 1e-6f);

    float o0 = fmaxf((h0 - med) * inv * w[t] + b[t], 0.0f);
    float o1 = fmaxf((h1 - med) * inv * w[t + 256] + b[t + 256], 0.0f);
    Exout[row * 512 + t]       = expf(o0);
    Exout[row * 512 + t + 256] = expf(o1);
}

// ---------------------------------------------------------------------------
extern "C" void kernel_launch(void* const* d_in, const int* in_sizes, int n_in,
                              void* d_out, int out_size) {
    const float* x    = (const float*)d_in[0];
    const float* w1   = (const float*)d_in[1];
    const float* b1   = (const float*)d_in[2];
    const float* ln1w = (const float*)d_in[3];
    const float* ln1b = (const float*)d_in[4];
    const float* w2   = (const float*)d_in[5];
    const float* b2   = (const float*)d_in[6];
    const float* ln2w = (const float*)d_in[7];
    const float* ln2b = (const float*)d_in[8];
    const float* w3   = (const float*)d_in[9];
    const float* b3   = (const float*)d_in[10];

    float *Ew1, *Ew2, *Ew3, *bufA, *bufB, *H;
    cudaGetSymbolAddress((void**)&Ew1, g_Ew1);
    cudaGetSymbolAddress((void**)&Ew2, g_Ew2);
    cudaGetSymbolAddress((void**)&Ew3, g_Ew3);
    cudaGetSymbolAddress((void**)&bufA, g_bufA);
    cudaGetSymbolAddress((void**)&bufB, g_bufB);
    cudaGetSymbolAddress((void**)&H, g_H);

    exp_all_kernel<<<1152, 256>>>(x, bufA, w1, Ew1, w2, Ew2, w3, Ew3);

    dim3 g1(512 / 64, 1024 / 64);   // 8 x 16 = 128 CTAs
    dim3 g3(256 / 64, 1024 / 32);   // 4 x 32 = 128 CTAs

    gemm_log_k<64><<<g1, 128>>>(bufA, Ew1, b1, H, 512);
    ln_kernel<<<1024, 256>>>(H, ln1w, ln1b, bufB);
    gemm_log_k<64><<<g1, 128>>>(bufB, Ew2, b2, H, 512);
    ln_kernel<<<1024, 256>>>(H, ln2w, ln2b, bufA);
    gemm_log_k<32><<<g3, 128>>>(bufA, Ew3, b3, (float*)d_out, 256);
}